// round 16
// baseline (speedup 1.0000x reference)
#include <cuda_runtime.h>
#include <cuda_fp16.h>
#include <cstdint>
#include <cstddef>

// KMeansLayer via mma.sync m16n8k16 (fp16 2-way split, 3 passes) + fused softmax.
// out[n,k] = softmax_k( 20*(x_n . c_k) - 10*||c_k||^2 )   (||x||^2 cancels)
// x: [32768, 256] f32, centroids: [512, 256] f32, out: [32768, 512] f32.
// R16: occupancy attack. MT=16 rows/CTA -> acc shrinks to 32 regs ->
//      __launch_bounds__(256,3) -> 3 CTAs/SM = 24 warps (6/SMSP), 1.5x
//      oversubscribed vs the ~4 needed to hide B's L2 latency. Barrier-free
//      loop, resident-A frags (16KB), B read per 4-nt chunk from L2/L1
//      (3 co-resident CTAs share the same B map -> L1 hits).

#define NRTOT   32768
#define KCLUST  512
#define DDIM    256
#define MT      16          // rows per CTA
#define NK      16          // k16 steps (DDIM/16)
#define NTHR    256
#define LOG2E   1.4426950408889634f

// device scratch
__device__ float g_csq10[KCLUST];
__device__ uint2 g_Bfrag[NK * 2 * 64 * 32];              // 0.5 MB fp16 B frags

// ---------------------------------------------------------------- helpers
__device__ __forceinline__ uint32_t packh2(float a, float b) {
    __half2 h = __floats2half2_rn(a, b);
    return *reinterpret_cast<uint32_t*>(&h);
}
__device__ __forceinline__ void mma16(float* d, const uint4& a, const uint2& b) {
    asm("mma.sync.aligned.m16n8k16.row.col.f32.f16.f16.f32 "
        "{%0,%1,%2,%3}, {%4,%5,%6,%7}, {%8,%9}, {%0,%1,%2,%3};"
        : "+f"(d[0]), "+f"(d[1]), "+f"(d[2]), "+f"(d[3])
        : "r"(a.x), "r"(a.y), "r"(a.z), "r"(a.w), "r"(b.x), "r"(b.y));
}

// ------------------------------------------------------ prologue: centroids
// One block per cluster n: 10*||c_n||^2 + fp16 hi/lo B fragments.
// Frag layout: g_Bfrag[((kc*2 + hl)*64 + nt)*32 + lane], uint2.
__global__ void prep_kernel(const float* __restrict__ cent) {
    __shared__ float cs[DDIM];
    __shared__ float part[64];
    const int n = blockIdx.x, t = threadIdx.x;

    if (t < 64) {
        float4 v = reinterpret_cast<const float4*>(cent)[n * (DDIM / 4) + t];
        reinterpret_cast<float4*>(cs)[t] = v;
        part[t] = v.x * v.x + v.y * v.y + v.z * v.z + v.w * v.w;
    }
    __syncthreads();
    if (t < 32) {
        float s = part[t] + part[t + 32];
#pragma unroll
        for (int o = 16; o > 0; o >>= 1) s += __shfl_xor_sync(0xffffffffu, s, o);
        if (t == 0) g_csq10[n] = 10.0f * s;
    }

    const int kc = t >> 3, hl = (t >> 2) & 1, tig = t & 3;
    const int k0 = kc * 16 + 2 * tig;
    const float v[4] = {cs[k0], cs[k0 + 1], cs[k0 + 8], cs[k0 + 9]};
    uint32_t p0, p1;
    if (hl == 0) {
        p0 = packh2(v[0], v[1]);
        p1 = packh2(v[2], v[3]);
    } else {
        float r[4];
#pragma unroll
        for (int i = 0; i < 4; ++i) {
            __half h = __float2half_rn(v[i]);
            r[i] = v[i] - __half2float(h);
        }
        p0 = packh2(r[0], r[1]);
        p1 = packh2(r[2], r[3]);
    }
    const int nt = n >> 3;
    const int lane = (n & 7) * 4 + tig;
    g_Bfrag[((kc * 2 + hl) * 64 + nt) * 32 + lane] = make_uint2(p0, p1);
}

// ------------------------------------------------------------ main kernel
// A-frag smem layout: afrag[((kc*2 + hl)*32 + lane)*4 + r] (uint32), 16KB.
__global__ __launch_bounds__(NTHR, 3)
void kmeans_mma(const float* __restrict__ x, float* __restrict__ out) {
    __shared__ uint32_t afrag[NK * 2 * 32 * 4];          // 16 KB resident A frags
    __shared__ float c10s[KCLUST];
    __shared__ float redM[MT * 8];
    __shared__ float redS[MT * 8];

    const int tid = threadIdx.x;
    const int nw = tid >> 5, lane = tid & 31;      // 8 warps, cols nw*64..
    const int grp = lane >> 2, tig = lane & 3;
    const int rowblk = blockIdx.x;

    for (int i = tid; i < KCLUST; i += NTHR) c10s[i] = g_csq10[i];

    // ---- one-time A conversion: thread owns (row = tid>>4, kc = tid&15) ----
    {
        const int row = tid >> 4, kc = tid & 15;
        const int rbit = row >> 3, rgrp = row & 7;
        const float* src = x + (size_t)(rowblk * MT + row) * DDIM + kc * 16;
        float f[16];
#pragma unroll
        for (int i = 0; i < 4; ++i) {
            float4 v = reinterpret_cast<const float4*>(src)[i];
            f[4 * i + 0] = v.x; f[4 * i + 1] = v.y;
            f[4 * i + 2] = v.z; f[4 * i + 3] = v.w;
        }
#pragma unroll
        for (int koff = 0; koff < 2; ++koff) {
#pragma unroll
            for (int tg = 0; tg < 4; ++tg) {
                const int li = koff * 8 + tg * 2;
                const float v0 = f[li], v1 = f[li + 1];
                const __half h0 = __float2half_rn(v0);
                const __half h1 = __float2half_rn(v1);
                const __half2 hh = __halves2half2(h0, h1);
                const uint32_t hi = *reinterpret_cast<const uint32_t*>(&hh);
                const uint32_t lo = packh2(v0 - __half2float(h0),
                                           v1 - __half2float(h1));
                const int ln = rgrp * 4 + tg;
                const int r = rbit + 2 * koff;
                afrag[((kc * 2 + 0) * 32 + ln) * 4 + r] = hi;
                afrag[((kc * 2 + 1) * 32 + ln) * 4 + r] = lo;
            }
        }
    }
    __syncthreads();   // afrag + c10s published; NO more syncs until epilogue

    float acc[8][4];
#pragma unroll
    for (int nt = 0; nt < 8; ++nt)
#pragma unroll
        for (int r = 0; r < 4; ++r) acc[nt][r] = 0.f;

    // ---- mainloop: per-warp k-stagger, B loaded per 4-nt chunk from L2/L1 ----
    int kk = nw * 2;                               // 8 warps span all 16 phases
    for (int k = 0; k < NK; ++k) {
        // A fragments for chunk kk (resident smem, conflict-free LDS.128)
        const uint4 ah = *reinterpret_cast<const uint4*>(
            &afrag[((kk * 2 + 0) * 32 + lane) * 4]);
        const uint4 al = *reinterpret_cast<const uint4*>(
            &afrag[((kk * 2 + 1) * 32 + lane) * 4]);

#pragma unroll
        for (int nc = 0; nc < 2; ++nc) {
            uint2 bh[4], bl[4];
#pragma unroll
            for (int j = 0; j < 4; ++j) {
                const int gnt = nw * 8 + nc * 4 + j;
                bh[j] = g_Bfrag[((kk * 2 + 0) * 64 + gnt) * 32 + lane];
                bl[j] = g_Bfrag[((kk * 2 + 1) * 64 + gnt) * 32 + lane];
            }
#pragma unroll
            for (int j = 0; j < 4; ++j) mma16(acc[nc * 4 + j], ah, bh[j]); // hi*hi
#pragma unroll
            for (int j = 0; j < 4; ++j) mma16(acc[nc * 4 + j], ah, bl[j]); // hi*lo
#pragma unroll
            for (int j = 0; j < 4; ++j) mma16(acc[nc * 4 + j], al, bh[j]); // lo*hi
        }

        if (++kk == NK) kk = 0;
    }

    // ---------------- fused softmax epilogue ----------------
#pragma unroll
    for (int nt = 0; nt < 8; ++nt)
#pragma unroll
        for (int r = 0; r < 4; ++r) {
            const int col = nw * 64 + nt * 8 + 2 * tig + (r & 1);
            acc[nt][r] = 20.f * acc[nt][r] - c10s[col];
        }

    float mloc[2];
#pragma unroll
    for (int rh = 0; rh < 2; ++rh) {
        float m = -1e30f;
#pragma unroll
        for (int nt = 0; nt < 8; ++nt) {
            m = fmaxf(m, acc[nt][rh * 2 + 0]);
            m = fmaxf(m, acc[nt][rh * 2 + 1]);
        }
        m = fmaxf(m, __shfl_xor_sync(0xffffffffu, m, 1));
        m = fmaxf(m, __shfl_xor_sync(0xffffffffu, m, 2));
        float s = 0.f;
#pragma unroll
        for (int nt = 0; nt < 8; ++nt) {
#pragma unroll
            for (int c = 0; c < 2; ++c) {
                const float e = exp2f((acc[nt][rh * 2 + c] - m) * LOG2E);
                acc[nt][rh * 2 + c] = e;         // reuse regs as exp values
                s += e;
            }
        }
        s += __shfl_xor_sync(0xffffffffu, s, 1);
        s += __shfl_xor_sync(0xffffffffu, s, 2);
        mloc[rh] = m;
        if (tig == 0) {
            const int row = rh * 8 + grp;
            redM[row * 8 + nw] = m;
            redS[row * 8 + nw] = s;
        }
    }
    __syncthreads();

#pragma unroll
    for (int rh = 0; rh < 2; ++rh) {
        const int row = rh * 8 + grp;
        float M = -1e30f;
        float mv[8];
#pragma unroll
        for (int j = 0; j < 8; ++j) {
            mv[j] = redM[row * 8 + j];
            M = fmaxf(M, mv[j]);
        }
        float S = 0.f;
#pragma unroll
        for (int j = 0; j < 8; ++j)
            S += redS[row * 8 + j] * exp2f((mv[j] - M) * LOG2E);
        const float scale = exp2f((mloc[rh] - M) * LOG2E) / S;

        float* orow = out + (size_t)(rowblk * MT + row) * KCLUST + nw * 64;
#pragma unroll
        for (int nt = 0; nt < 8; ++nt) {
            float2 v;
            v.x = acc[nt][rh * 2 + 0] * scale;
            v.y = acc[nt][rh * 2 + 1] * scale;
            *reinterpret_cast<float2*>(orow + nt * 8 + 2 * tig) = v;
        }
    }
}

// ---------------------------------------------------------------- launch
extern "C" void kernel_launch(void* const* d_in, const int* in_sizes, int n_in,
                              void* d_out, int out_size) {
    const float* x = (const float*)d_in[0];
    const float* cent = (const float*)d_in[1];
    if (n_in >= 2 && in_sizes[0] == KCLUST * DDIM && in_sizes[1] == NRTOT * DDIM) {
        const float* t = x; x = cent; cent = t;
    }
    float* out = (float*)d_out;

    prep_kernel<<<KCLUST, 128>>>(cent);
    kmeans_mma<<<NRTOT / MT, NTHR>>>(x, out);
}

// round 17
// speedup vs baseline: 1.4907x; 1.4907x over previous
#include <cuda_runtime.h>
#include <cuda_fp16.h>
#include <cstdint>
#include <cstddef>

// KMeansLayer via mma.sync m16n8k16 (fp16 2-way split, 3 passes) + fused softmax.
// out[n,k] = softmax_k( 20*(x_n . c_k) - 10*||c_k||^2 )   (||x||^2 cancels)
// x: [32768, 256] f32, centroids: [512, 256] f32, out: [32768, 512] f32.
// R17: R10's smem-B cp.async ring (NST=2, one barrier/step) + R14's resident
//      smem A fragments (one-time conversion). Per-step warp work collapses to
//      4 A-LDS.128 + 8 B-LDS.128 (hi/lo interleaved) + 48 HMMA.
//      MT=32, 256 thr, 2 CTAs/SM.

#define NRTOT   32768
#define KCLUST  512
#define DDIM    256
#define MT      32          // rows per CTA
#define NK      16          // k16 steps (DDIM/16)
#define NST     2           // B pipeline stages
#define NTHR    256
#define LOG2E   1.4426950408889634f

#define B_STG_BYTES 32768   // [nt 64][lane 32][hl 2] uint2 = 32KB per k-chunk
#define SMEM_DYN    (NST * B_STG_BYTES)                  // 64KB dynamic

// device scratch
__device__ float g_csq10[KCLUST];
__device__ uint2 g_Bfrag[NK * 64 * 32 * 2];              // 0.5 MB fp16 B frags

// ---------------------------------------------------------------- helpers
__device__ __forceinline__ uint32_t smem_u32(const void* p) {
    uint32_t a;
    asm("{ .reg .u64 t; cvta.to.shared.u64 t, %1; cvt.u32.u64 %0, t; }"
        : "=r"(a) : "l"(p));
    return a;
}
__device__ __forceinline__ uint32_t packh2(float a, float b) {
    __half2 h = __floats2half2_rn(a, b);
    return *reinterpret_cast<uint32_t*>(&h);
}
__device__ __forceinline__ void cp16(uint32_t dst, const void* src) {
    asm volatile("cp.async.cg.shared.global [%0], [%1], 16;"
                 :: "r"(dst), "l"(__cvta_generic_to_global(src)) : "memory");
}
#define CP_COMMIT() asm volatile("cp.async.commit_group;" ::: "memory")
#define CP_WAIT0()  asm volatile("cp.async.wait_group 0;" ::: "memory")

__device__ __forceinline__ void mma16(float* d, const uint4& a, const uint2& b) {
    asm("mma.sync.aligned.m16n8k16.row.col.f32.f16.f16.f32 "
        "{%0,%1,%2,%3}, {%4,%5,%6,%7}, {%8,%9}, {%0,%1,%2,%3};"
        : "+f"(d[0]), "+f"(d[1]), "+f"(d[2]), "+f"(d[3])
        : "r"(a.x), "r"(a.y), "r"(a.z), "r"(a.w), "r"(b.x), "r"(b.y));
}

// ------------------------------------------------------ prologue: centroids
// One block per cluster n: 10*||c_n||^2 + fp16 hi/lo B fragments.
// Frag layout: g_Bfrag[((kc*64 + nt)*32 + lane)*2 + hl], uint2 -- so one
// LDS.128 in the mainloop yields {bh0, bh1, bl0, bl1} for an (nt, lane).
__global__ void prep_kernel(const float* __restrict__ cent) {
    __shared__ float cs[DDIM];
    __shared__ float part[64];
    const int n = blockIdx.x, t = threadIdx.x;

    if (t < 64) {
        float4 v = reinterpret_cast<const float4*>(cent)[n * (DDIM / 4) + t];
        reinterpret_cast<float4*>(cs)[t] = v;
        part[t] = v.x * v.x + v.y * v.y + v.z * v.z + v.w * v.w;
    }
    __syncthreads();
    if (t < 32) {
        float s = part[t] + part[t + 32];
#pragma unroll
        for (int o = 16; o > 0; o >>= 1) s += __shfl_xor_sync(0xffffffffu, s, o);
        if (t == 0) g_csq10[n] = 10.0f * s;
    }

    const int kc = t >> 3, hl = (t >> 2) & 1, tig = t & 3;
    const int k0 = kc * 16 + 2 * tig;
    const float v[4] = {cs[k0], cs[k0 + 1], cs[k0 + 8], cs[k0 + 9]};
    uint32_t p0, p1;
    if (hl == 0) {
        p0 = packh2(v[0], v[1]);
        p1 = packh2(v[2], v[3]);
    } else {
        float r[4];
#pragma unroll
        for (int i = 0; i < 4; ++i) {
            __half h = __float2half_rn(v[i]);
            r[i] = v[i] - __half2float(h);
        }
        p0 = packh2(r[0], r[1]);
        p1 = packh2(r[2], r[3]);
    }
    const int nt = n >> 3;
    const int lane = (n & 7) * 4 + tig;
    g_Bfrag[((kc * 64 + nt) * 32 + lane) * 2 + hl] = make_uint2(p0, p1);
}

// ------------------------------------------------------------ main kernel
// B stage slot: one kc block of g_Bfrag, copied linearly (32KB).
__device__ __forceinline__ void issue_stage(uint32_t sb, int s, int kc, int tid) {
    const uint32_t dst0 = sb + s * B_STG_BYTES;
    const char* gB = reinterpret_cast<const char*>(g_Bfrag) +
                     (size_t)kc * B_STG_BYTES;
#pragma unroll
    for (int j = 0; j < 8; ++j) {
        const int o = (tid + j * NTHR) * 16;
        cp16(dst0 + o, gB + o);
    }
}

// A-frag smem layout: afrag[(((kc*2 + hl)*2 + mt)*32 + lane)*4 + r] (uint32)
__global__ __launch_bounds__(NTHR, 2)
void kmeans_mma(const float* __restrict__ x, float* __restrict__ out) {
    __shared__ uint32_t afrag[NK * 2 * 2 * 32 * 4];      // 32 KB resident A frags
    __shared__ float c10s[KCLUST];
    __shared__ float redM[MT * 8];
    __shared__ float redS[MT * 8];
    extern __shared__ char smem[];                       // B stages (64KB)
    const uint32_t sb = smem_u32(smem);

    const int tid = threadIdx.x;
    const int nw = tid >> 5, lane = tid & 31;      // 8 warps, all cover rows 0..31
    const int grp = lane >> 2, tig = lane & 3;
    const int rowblk = blockIdx.x;

    for (int i = tid; i < KCLUST; i += NTHR) c10s[i] = g_csq10[i];

    // ---- one-time A conversion: thread owns (row = tid>>3, k-chunk = tid&7) ----
    {
        const int row = tid >> 3, chunk = tid & 7;
        const int mt = row >> 4, rbit = (row >> 3) & 1, rgrp = row & 7;
        const float* src = x + (size_t)(rowblk * MT + row) * DDIM + chunk * 32;
        float f[32];
#pragma unroll
        for (int i = 0; i < 8; ++i) {
            float4 v = reinterpret_cast<const float4*>(src)[i];
            f[4 * i + 0] = v.x; f[4 * i + 1] = v.y;
            f[4 * i + 2] = v.z; f[4 * i + 3] = v.w;
        }
#pragma unroll
        for (int kc2 = 0; kc2 < 2; ++kc2) {
            const int kc = chunk * 2 + kc2;
#pragma unroll
            for (int koff = 0; koff < 2; ++koff) {
#pragma unroll
                for (int tg = 0; tg < 4; ++tg) {
                    const int li = kc2 * 16 + koff * 8 + tg * 2;
                    const float v0 = f[li], v1 = f[li + 1];
                    const __half h0 = __float2half_rn(v0);
                    const __half h1 = __float2half_rn(v1);
                    const __half2 hh = __halves2half2(h0, h1);
                    const uint32_t hi = *reinterpret_cast<const uint32_t*>(&hh);
                    const uint32_t lo = packh2(v0 - __half2float(h0),
                                               v1 - __half2float(h1));
                    const int ln = rgrp * 4 + tg;
                    const int r = rbit + 2 * koff;
                    afrag[(((kc * 2 + 0) * 2 + mt) * 32 + ln) * 4 + r] = hi;
                    afrag[(((kc * 2 + 1) * 2 + mt) * 32 + ln) * 4 + r] = lo;
                }
            }
        }
    }

    float acc[2][8][4];
#pragma unroll
    for (int mt = 0; mt < 2; ++mt)
#pragma unroll
        for (int nt = 0; nt < 8; ++nt)
#pragma unroll
            for (int r = 0; r < 4; ++r) acc[mt][nt][r] = 0.f;

    // B pipeline prologue: fill slot 0 with stage 0
    issue_stage(sb, 0, 0, tid);
    CP_COMMIT();
    CP_WAIT0();
    __syncthreads();   // afrag + c10s + B stage 0 published

    for (int k = 0; k < NK; ++k) {
        // issue stage k+1 into slot (k+1)&1 (freed by end-of-step-(k-1) barrier)
        if (k + 1 < NK) {
            issue_stage(sb, (k + 1) & 1, k + 1, tid);
            CP_COMMIT();
        }

        // ---- consume stage k ----
        uint4 ah[2], al[2];
#pragma unroll
        for (int mt = 0; mt < 2; ++mt) {
            ah[mt] = *reinterpret_cast<const uint4*>(
                &afrag[(((k * 2 + 0) * 2 + mt) * 32 + lane) * 4]);
            al[mt] = *reinterpret_cast<const uint4*>(
                &afrag[(((k * 2 + 1) * 2 + mt) * 32 + lane) * 4]);
        }

        const uint4* sB4 = reinterpret_cast<const uint4*>(smem + (k & 1) * B_STG_BYTES);
#pragma unroll
        for (int nc = 0; nc < 2; ++nc) {
            uint2 bh[4], bl[4];
#pragma unroll
            for (int j = 0; j < 4; ++j) {
                const uint4 v = sB4[(nw * 8 + nc * 4 + j) * 32 + lane];
                bh[j] = make_uint2(v.x, v.y);
                bl[j] = make_uint2(v.z, v.w);
            }
#pragma unroll
            for (int j = 0; j < 4; ++j) {           // hi*hi
                mma16(acc[0][nc * 4 + j], ah[0], bh[j]);
                mma16(acc[1][nc * 4 + j], ah[1], bh[j]);
            }
#pragma unroll
            for (int j = 0; j < 4; ++j) {           // hi*lo
                mma16(acc[0][nc * 4 + j], ah[0], bl[j]);
                mma16(acc[1][nc * 4 + j], ah[1], bl[j]);
            }
#pragma unroll
            for (int j = 0; j < 4; ++j) {           // lo*hi
                mma16(acc[0][nc * 4 + j], al[0], bh[j]);
                mma16(acc[1][nc * 4 + j], al[1], bh[j]);
            }
        }

        // end of step: stage k+1 landed + all warps done with slot k&1
        if (k + 1 < NK) {
            CP_WAIT0();
            __syncthreads();
        }
    }

    // ---------------- fused softmax epilogue ----------------
#pragma unroll
    for (int mt = 0; mt < 2; ++mt)
#pragma unroll
        for (int nt = 0; nt < 8; ++nt)
#pragma unroll
            for (int r = 0; r < 4; ++r) {
                const int col = nw * 64 + nt * 8 + 2 * tig + (r & 1);
                acc[mt][nt][r] = 20.f * acc[mt][nt][r] - c10s[col];
            }

    float mloc[4];
#pragma unroll
    for (int rid = 0; rid < 4; ++rid) {
        const int mt = rid >> 1, rh = rid & 1;
        float m = -1e30f;
#pragma unroll
        for (int nt = 0; nt < 8; ++nt) {
            m = fmaxf(m, acc[mt][nt][rh * 2 + 0]);
            m = fmaxf(m, acc[mt][nt][rh * 2 + 1]);
        }
        m = fmaxf(m, __shfl_xor_sync(0xffffffffu, m, 1));
        m = fmaxf(m, __shfl_xor_sync(0xffffffffu, m, 2));
        float s = 0.f;
#pragma unroll
        for (int nt = 0; nt < 8; ++nt) {
#pragma unroll
            for (int c = 0; c < 2; ++c) {
                const float e = exp2f((acc[mt][nt][rh * 2 + c] - m) * LOG2E);
                acc[mt][nt][rh * 2 + c] = e;     // reuse regs as exp values
                s += e;
            }
        }
        s += __shfl_xor_sync(0xffffffffu, s, 1);
        s += __shfl_xor_sync(0xffffffffu, s, 2);
        mloc[rid] = m;
        if (tig == 0) {
            const int row = mt * 16 + rh * 8 + grp;
            redM[row * 8 + nw] = m;
            redS[row * 8 + nw] = s;
        }
    }
    __syncthreads();

#pragma unroll
    for (int rid = 0; rid < 4; ++rid) {
        const int mt = rid >> 1, rh = rid & 1;
        const int row = mt * 16 + rh * 8 + grp;
        float M = -1e30f;
        float mv[8];
#pragma unroll
        for (int j = 0; j < 8; ++j) {
            mv[j] = redM[row * 8 + j];
            M = fmaxf(M, mv[j]);
        }
        float S = 0.f;
#pragma unroll
        for (int j = 0; j < 8; ++j)
            S += redS[row * 8 + j] * exp2f((mv[j] - M) * LOG2E);
        const float scale = exp2f((mloc[rid] - M) * LOG2E) / S;

        float* orow = out + (size_t)(rowblk * MT + row) * KCLUST + nw * 64;
#pragma unroll
        for (int nt = 0; nt < 8; ++nt) {
            float2 v;
            v.x = acc[mt][nt][rh * 2 + 0] * scale;
            v.y = acc[mt][nt][rh * 2 + 1] * scale;
            *reinterpret_cast<float2*>(orow + nt * 8 + 2 * tig) = v;
        }
    }
}

// ---------------------------------------------------------------- launch
extern "C" void kernel_launch(void* const* d_in, const int* in_sizes, int n_in,
                              void* d_out, int out_size) {
    const float* x = (const float*)d_in[0];
    const float* cent = (const float*)d_in[1];
    if (n_in >= 2 && in_sizes[0] == KCLUST * DDIM && in_sizes[1] == NRTOT * DDIM) {
        const float* t = x; x = cent; cent = t;
    }
    float* out = (float*)d_out;

    cudaFuncSetAttribute(kmeans_mma,
                         cudaFuncAttributeMaxDynamicSharedMemorySize,
                         SMEM_DYN);

    prep_kernel<<<KCLUST, 128>>>(cent);
    kmeans_mma<<<NRTOT / MT, NTHR, SMEM_DYN>>>(x, out);
}